// round 2
// baseline (speedup 1.0000x reference)
#include <cuda_runtime.h>
#include <math.h>

#define N_NODES   20000
#define N_EDGES   320000
#define MUL0      64
#define NODE_DIM  240          // 64 + 3*32 + 5*16
#define NUM_BASIS 16
#define NCH       112          // 64 + 32 + 16 fused channels
#define INV_SQRT_MAXAT 0.0916698497028211f   // 1/sqrt(119)

// Fused projection matrices: M[b][ch] includes one_scalar and 1/sqrt(64)
__device__ float g_M[NUM_BASIS * NCH];
// counting-sort scratch
__device__ int g_deg[N_NODES];
__device__ int g_offs[N_NODES + 1];
__device__ int g_cursor[N_NODES];
__device__ int g_sorted[N_EDGES];

// ---------------------------------------------------------------------------
// K1: zero histogram + precompute fused M (merged)
// ---------------------------------------------------------------------------
__global__ void setup_kernel(const float* __restrict__ W_rbf,
                             const float* __restrict__ w_expand,
                             const float* __restrict__ b_expand,
                             const float* __restrict__ Wp0,
                             const float* __restrict__ Wp1,
                             const float* __restrict__ Wp2)
{
    int idx = blockIdx.x * blockDim.x + threadIdx.x;
    if (idx < N_NODES) g_deg[idx] = 0;
    if (idx >= NUM_BASIS * NCH) return;
    int b  = idx / NCH;
    int ch = idx % NCH;
    float acc = 0.f;
    if (ch < 64) {
        int d = ch;
        #pragma unroll 8
        for (int c = 0; c < 64; ++c)
            acc += W_rbf[b * 192 + c] * (w_expand[c] + b_expand[c]) * Wp0[c * 64 + d];
    } else if (ch < 96) {
        int d = ch - 64;
        #pragma unroll 8
        for (int c = 0; c < 64; ++c)
            acc += W_rbf[b * 192 + 64 + c] * (w_expand[c] + b_expand[c]) * Wp1[c * 32 + d];
    } else {
        int d = ch - 96;
        #pragma unroll 8
        for (int c = 0; c < 64; ++c)
            acc += W_rbf[b * 192 + 128 + c] * (w_expand[c] + b_expand[c]) * Wp2[c * 16 + d];
    }
    g_M[b * NCH + ch] = acc * 0.125f;   // * 1/sqrt(64)
}

// ---------------------------------------------------------------------------
// K2: per-edge rbf + rsh outputs + dst histogram (no projection, no fp atomics)
// ---------------------------------------------------------------------------
__global__ void __launch_bounds__(256)
edge_kernel(const float* __restrict__ pos,
            const int*   __restrict__ edge_index,
            float*       __restrict__ rbf_out,
            float*       __restrict__ rsh_out)
{
    int e = blockIdx.x * blockDim.x + threadIdx.x;
    if (e >= N_EDGES) return;

    int src = edge_index[e];
    int dst = edge_index[N_EDGES + e];

    const float* Ps = pos + 3 * src;
    const float* Pd = pos + 3 * dst;
    // reference permutes pos columns to [1,2,0] before differencing
    float vx = Pd[1] - Ps[1];
    float vy = Pd[2] - Ps[2];
    float vz = Pd[0] - Ps[0];

    float d2   = vx * vx + vy * vy + vz * vz;
    float dist = sqrtf(d2);
    float dcl  = fmaxf(dist, 1e-8f);
    float uinv = 1.0f / dcl;
    float x = vx * uinv, y = vy * uinv, z = vz * uinv;

    const float s3  = 1.7320508075688772f;
    const float s5  = 2.23606797749979f;
    const float s15 = 3.872983346207417f;

    float sh[9];
    sh[0] = 1.f;
    sh[1] = s3 * x;
    sh[2] = s3 * y;
    sh[3] = s3 * z;
    sh[4] = s15 * x * z;
    sh[5] = s15 * x * y;
    sh[6] = s5 * (y * y - 0.5f * (x * x + z * z));
    sh[7] = s15 * y * z;
    sh[8] = 0.5f * s15 * (z * z - x * x);

    {
        float* ro = rsh_out + (size_t)e * 9;
        #pragma unroll
        for (int i = 0; i < 9; ++i) ro[i] = sh[i];
    }

    float rbf[16];
    if (dcl < 5.0f) {
        float X  = dcl * 0.2f;
        float X2 = X * X;
        float X5 = X2 * X2 * X;
        float fc = 1.0f + X5 * (-21.0f + X * (35.0f - 15.0f * X));
        float theta = 3.14159265358979323846f * X;
        float s1 = sinf(theta), c1 = cosf(theta);
        float two  = 2.0f * c1;
        float pref = 0.6324555320336759f * uinv * fc;   // sqrt(2/5)/d * fc
        float sp = 0.f, s = s1;
        #pragma unroll
        for (int n = 0; n < 16; ++n) {
            rbf[n] = pref * s;
            float sn = two * s - sp;
            sp = s; s = sn;
        }
    } else {
        #pragma unroll
        for (int n = 0; n < 16; ++n) rbf[n] = 0.f;
    }

    {
        float4* ro = (float4*)(rbf_out + (size_t)e * 16);
        #pragma unroll
        for (int q = 0; q < 4; ++q)
            ro[q] = make_float4(rbf[4 * q], rbf[4 * q + 1], rbf[4 * q + 2], rbf[4 * q + 3]);
    }

    atomicAdd(&g_deg[dst], 1);
}

// ---------------------------------------------------------------------------
// K3: single-block exclusive scan over the 20000-bin histogram
// ---------------------------------------------------------------------------
__global__ void scan_kernel()
{
    __shared__ int sh[1024];
    const int CHUNK = 20;              // 1024*20 = 20480 >= 20000
    int t = threadIdx.x;
    int base = t * CHUNK;
    int local[CHUNK];
    int sum = 0;
    #pragma unroll
    for (int i = 0; i < CHUNK; ++i) {
        int idx = base + i;
        int v = (idx < N_NODES) ? g_deg[idx] : 0;
        local[i] = sum;                // exclusive within chunk
        sum += v;
    }
    sh[t] = sum;
    __syncthreads();
    for (int off = 1; off < 1024; off <<= 1) {
        int v = (t >= off) ? sh[t - off] : 0;
        __syncthreads();
        sh[t] += v;
        __syncthreads();
    }
    int pre = (t > 0) ? sh[t - 1] : 0;
    #pragma unroll
    for (int i = 0; i < CHUNK; ++i) {
        int idx = base + i;
        if (idx < N_NODES) {
            int o = pre + local[i];
            g_offs[idx]   = o;
            g_cursor[idx] = o;
        }
    }
    if (t == 1023) g_offs[N_NODES] = sh[1023];
}

// ---------------------------------------------------------------------------
// K4: scatter edge ids into dst-sorted order
// ---------------------------------------------------------------------------
__global__ void __launch_bounds__(256)
scatter_kernel(const int* __restrict__ edge_index)
{
    int e = blockIdx.x * blockDim.x + threadIdx.x;
    if (e >= N_EDGES) return;
    int dst = edge_index[N_EDGES + e];
    int p = atomicAdd(&g_cursor[dst], 1);
    g_sorted[p] = e;
}

// ---------------------------------------------------------------------------
// K5: warp-per-node gather + sufficient-statistics + single projection
//
// Stats layout (144 per node):
//   s in [0,16)   : G0[b]      = sum_e rbf[b]            (b = s)
//   s in [16,144) : j=(s-16)>>4 in 0..7, b=(s-16)&15
//                   = sum_e rbf[b]*sh[1+j]
//   (j=0..2 -> G1[m=j], j=3..7 -> G2[m=j-3])
// Lane l owns slots s = l + 32q, q=0..4 (s<144).
// ---------------------------------------------------------------------------
__global__ void __launch_bounds__(256)
node_kernel(const int*   __restrict__ at_no,
            const float* __restrict__ W_atom,
            const float* __restrict__ b_atom,
            const float* __restrict__ rbf_out,
            const float* __restrict__ rsh_out,
            float*       __restrict__ node_emb)
{
    __shared__ float sM[NUM_BASIS * NCH];      // 1792 floats
    __shared__ float sG[8][144];               // per-warp stats

    for (int i = threadIdx.x; i < NUM_BASIS * NCH; i += blockDim.x)
        sM[i] = g_M[i];
    __syncthreads();

    int warp = threadIdx.x >> 5;
    int lane = threadIdx.x & 31;
    int n = blockIdx.x * 8 + warp;
    if (n >= N_NODES) return;

    // per-lane shuffle sources for the 5 slots
    int srcA[5], srcB[5];
    bool valid[5];
    #pragma unroll
    for (int q = 0; q < 5; ++q) {
        int s = lane + 32 * q;
        valid[q] = (s < 144);
        if (s < 16)      { srcA[q] = s;            srcB[q] = 31; }      // *1.0
        else if (s < 144){ int t = s - 16; srcA[q] = t & 15; srcB[q] = 17 + (t >> 4); }
        else             { srcA[q] = 0;            srcB[q] = 0; }
    }

    float acc[5] = {0.f, 0.f, 0.f, 0.f, 0.f};

    int k0 = g_offs[n];
    int k1 = g_offs[n + 1];

    int eid = (k0 < k1) ? g_sorted[k0] : 0;
    for (int k = k0; k < k1; ++k) {
        int eid_next = (k + 1 < k1) ? g_sorted[k + 1] : 0;

        // L: lanes 0-15 rbf[b], lanes 16-24 sh[lane-16], lanes 25-31 = 1.0
        float L = 1.0f;
        if (lane < 16)      L = rbf_out[(size_t)eid * 16 + lane];
        else if (lane < 25) L = rsh_out[(size_t)eid * 9 + (lane - 16)];

        #pragma unroll
        for (int q = 0; q < 5; ++q) {
            float a = __shfl_sync(0xffffffffu, L, srcA[q]);
            float b = __shfl_sync(0xffffffffu, L, srcB[q]);
            if (valid[q]) acc[q] = fmaf(a, b, acc[q]);
        }
        eid = eid_next;
    }

    // stage stats to shared
    #pragma unroll
    for (int q = 0; q < 5; ++q)
        if (valid[q]) sG[warp][lane + 32 * q] = acc[q];
    __syncwarp();

    const float* G = sG[warp];
    int an = at_no[n];
    float* nrow = node_emb + (size_t)n * NODE_DIM;

    #pragma unroll
    for (int q = 0; q < 8; ++q) {
        int ch = lane + 32 * q;
        if (ch < NODE_DIM) {
            float a = 0.f;
            if (ch < 64) {
                #pragma unroll
                for (int b = 0; b < 16; ++b)
                    a = fmaf(G[b], sM[b * NCH + ch], a);
                a += W_atom[an * MUL0 + ch] * INV_SQRT_MAXAT + b_atom[ch];
            } else if (ch < 160) {
                int t = ch - 64;
                int d = t / 3, m = t - 3 * d;          // ch = 64 + 3d + m
                const float* Gp = G + 16 + m * 16;     // G1[m][.]
                #pragma unroll
                for (int b = 0; b < 16; ++b)
                    a = fmaf(Gp[b], sM[b * NCH + 64 + d], a);
            } else {
                int t = ch - 160;
                int d = t / 5, m = t - 5 * d;          // ch = 160 + 5d + m
                const float* Gp = G + 64 + m * 16;     // G2[m][.]
                #pragma unroll
                for (int b = 0; b < 16; ++b)
                    a = fmaf(Gp[b], sM[b * NCH + 96 + d], a);
            }
            nrow[ch] = a;
        }
    }
}

// ---------------------------------------------------------------------------
// Launch
// ---------------------------------------------------------------------------
extern "C" void kernel_launch(void* const* d_in, const int* in_sizes, int n_in,
                              void* d_out, int out_size)
{
    const int*   at_no      = (const int*)  d_in[0];
    const float* pos        = (const float*)d_in[1];
    const int*   edge_index = (const int*)  d_in[2];
    const float* W_atom     = (const float*)d_in[3];
    const float* b_atom     = (const float*)d_in[4];
    const float* w_expand   = (const float*)d_in[5];
    const float* b_expand   = (const float*)d_in[6];
    const float* W_rbf      = (const float*)d_in[7];
    const float* Wp0        = (const float*)d_in[8];
    const float* Wp1        = (const float*)d_in[9];
    const float* Wp2        = (const float*)d_in[10];

    float* out      = (float*)d_out;
    float* node_emb = out;                                   // 20000*240
    float* rbf_out  = out + (size_t)N_NODES * NODE_DIM;      // 320000*16
    float* rsh_out  = rbf_out + (size_t)N_EDGES * NUM_BASIS; // 320000*9

    setup_kernel<<<(N_NODES + 255) / 256, 256>>>(W_rbf, w_expand, b_expand,
                                                 Wp0, Wp1, Wp2);
    edge_kernel<<<(N_EDGES + 255) / 256, 256>>>(pos, edge_index, rbf_out, rsh_out);
    scan_kernel<<<1, 1024>>>();
    scatter_kernel<<<(N_EDGES + 255) / 256, 256>>>(edge_index);
    node_kernel<<<(N_NODES + 7) / 8, 256>>>(at_no, W_atom, b_atom,
                                            rbf_out, rsh_out, node_emb);
}